// round 7
// baseline (speedup 1.0000x reference)
#include <cuda_runtime.h>
#include <math.h>

#define NN   50000
#define EE   300000
#define TOTE (EE + NN)
#define GG   64
#define NB_SCAN 196   // ceil(NN/256)

typedef unsigned long long u64;

// ---------------- scratch (device globals; no allocation allowed) ----------
__device__ float4 g_xw4[NN * 64];   // x @ W   [N, 256] viewed as [N, 64] float4
__device__ float  g_as[NN * 2];
__device__ float  g_ad[NN * 2];
__device__ int    g_deg[NN];
__device__ int    g_off[NN];
__device__ int    g_woff[NN];
__device__ int    g_srcs[TOTE];
__device__ float  g_z[NN * 3];
__device__ int    g_bsum[256];

// ---------------- packed f32x2 helpers ---------------------------------------
__device__ __forceinline__ void fma2(u64& d, u64 a, u64 b) {
    asm("fma.rn.f32x2 %0, %1, %2, %0;" : "+l"(d) : "l"(a), "l"(b));
}
__device__ __forceinline__ u64 bcast2(float x) {
    u64 r;
    asm("mov.b64 %0, {%1, %1};" : "=l"(r) : "f"(x));
    return r;
}
__device__ __forceinline__ void unpack2(u64 v, float& lo, float& hi) {
    asm("mov.b64 {%0, %1}, %2;" : "=f"(lo), "=f"(hi) : "l"(v));
}

// ---------------- kernels ----------------------------------------------------
__global__ void k_init() {
    int i = blockIdx.x * blockDim.x + threadIdx.x;
    if (i < NN) g_deg[i] = 0;
}

// Tiled GEMM with packed f32x2 FMA: 64 nodes x 256 cols per block;
// thread = 8 nodes x 8 cols (4 packed col-pairs). Fused a_s/a_d epilogue.
__global__ __launch_bounds__(256) void k_gemm(const float* __restrict__ x,
                                              const float* __restrict__ W,
                                              const float* __restrict__ att_s,
                                              const float* __restrict__ att_d) {
    extern __shared__ float sm[];
    float* xs = sm;                 // [128][68], xs[k*68 + node]
    float* ws = sm + 128 * 68;      // [32][256]

    int tid = threadIdx.x;
    int tx = tid & 31;              // col group: cols tx*8 .. tx*8+7
    int ty = tid >> 5;              // node group: nodes ty*8 .. +7
    int n0 = blockIdx.x * 64;

    // load x tile transposed (zero-pad past NN)
#pragma unroll
    for (int r = 0; r < 8; r++) {
        int lin4 = r * 256 + tid;
        int node = lin4 >> 5;
        int k = (lin4 & 31) * 4;
        float4 v = make_float4(0.f, 0.f, 0.f, 0.f);
        if (n0 + node < NN) v = ((const float4*)x)[(size_t)(n0 + node) * 32 + (lin4 & 31)];
        xs[(k + 0) * 68 + node] = v.x;
        xs[(k + 1) * 68 + node] = v.y;
        xs[(k + 2) * 68 + node] = v.z;
        xs[(k + 3) * 68 + node] = v.w;
    }

    u64 acc2[8][4];
#pragma unroll
    for (int i = 0; i < 8; i++)
#pragma unroll
        for (int j = 0; j < 4; j++) acc2[i][j] = 0ull;

    for (int kc = 0; kc < 4; kc++) {
        __syncthreads();
#pragma unroll
        for (int r = 0; r < 8; r++) {
            int lin4 = r * 256 + tid;
            ((float4*)ws)[lin4] = ((const float4*)W)[kc * 2048 + lin4];
        }
        __syncthreads();
#pragma unroll 8
        for (int k = 0; k < 32; k++) {
            const float* xr = &xs[(kc * 32 + k) * 68 + ty * 8];
            float4 a0 = *(const float4*)(xr);
            float4 a1 = *(const float4*)(xr + 4);
            u64 xp[8] = {bcast2(a0.x), bcast2(a0.y), bcast2(a0.z), bcast2(a0.w),
                         bcast2(a1.x), bcast2(a1.y), bcast2(a1.z), bcast2(a1.w)};
            const u64* wr = (const u64*)&ws[k * 256 + tx * 8];
            u64 w0 = wr[0], w1 = wr[1], w2 = wr[2], w3 = wr[3];
#pragma unroll
            for (int i = 0; i < 8; i++) {
                fma2(acc2[i][0], xp[i], w0);
                fma2(acc2[i][1], xp[i], w1);
                fma2(acc2[i][2], xp[i], w2);
                fma2(acc2[i][3], xp[i], w3);
            }
        }
    }

    // unpack accumulators, then epilogue: store xw + fused a_s/a_d
    int head = (tx < 16) ? 0 : 1;
    float4 s0 = ((const float4*)att_s)[tx * 2];
    float4 s1 = ((const float4*)att_s)[tx * 2 + 1];
    float4 d0 = ((const float4*)att_d)[tx * 2];
    float4 d1 = ((const float4*)att_d)[tx * 2 + 1];
#pragma unroll
    for (int i = 0; i < 8; i++) {
        float acc[8];
#pragma unroll
        for (int j = 0; j < 4; j++) unpack2(acc2[i][j], acc[2 * j], acc[2 * j + 1]);
        int node = n0 + ty * 8 + i;
        float sp = acc[0] * s0.x + acc[1] * s0.y + acc[2] * s0.z + acc[3] * s0.w
                 + acc[4] * s1.x + acc[5] * s1.y + acc[6] * s1.z + acc[7] * s1.w;
        float dp = acc[0] * d0.x + acc[1] * d0.y + acc[2] * d0.z + acc[3] * d0.w
                 + acc[4] * d1.x + acc[5] * d1.y + acc[6] * d1.z + acc[7] * d1.w;
#pragma unroll
        for (int off = 1; off < 16; off <<= 1) {
            sp += __shfl_xor_sync(0xffffffffu, sp, off);
            dp += __shfl_xor_sync(0xffffffffu, dp, off);
        }
        if (node < NN) {
            g_xw4[(size_t)node * 64 + tx * 2]     = make_float4(acc[0], acc[1], acc[2], acc[3]);
            g_xw4[(size_t)node * 64 + tx * 2 + 1] = make_float4(acc[4], acc[5], acc[6], acc[7]);
            if ((tx & 15) == 0) {
                g_as[2 * node + head] = sp;
                g_ad[2 * node + head] = dp;
            }
        }
    }
}

// degree histogram of targets
__global__ void k_deg(const int* __restrict__ ei) {
    int e = blockIdx.x * blockDim.x + threadIdx.x;
    if (e >= TOTE) return;
    int t = (e < EE) ? ei[EE + e] : (e - EE);
    if ((unsigned)t < NN) atomicAdd(&g_deg[t], 1);
}

// parallel scan, 3 stages
__global__ void k_scan1() {
    __shared__ int sp[256];
    int t = threadIdx.x;
    int i = blockIdx.x * 256 + t;
    sp[t] = (i < NN) ? g_deg[i] : 0;
    __syncthreads();
    for (int off = 128; off; off >>= 1) {
        if (t < off) sp[t] += sp[t + off];
        __syncthreads();
    }
    if (t == 0) g_bsum[blockIdx.x] = sp[0];
}
__global__ void k_scan2() {
    __shared__ int sp[256];
    int t = threadIdx.x;
    int v = (t < NB_SCAN) ? g_bsum[t] : 0;
    sp[t] = v;
    __syncthreads();
    for (int off = 1; off < 256; off <<= 1) {
        int u = (t >= off) ? sp[t - off] : 0;
        __syncthreads();
        sp[t] += u;
        __syncthreads();
    }
    g_bsum[t] = sp[t] - v;
}
__global__ void k_scan3() {
    __shared__ int sp[256];
    int t = threadIdx.x;
    int i = blockIdx.x * 256 + t;
    int v = (i < NN) ? g_deg[i] : 0;
    sp[t] = v;
    __syncthreads();
    for (int off = 1; off < 256; off <<= 1) {
        int u = (t >= off) ? sp[t - off] : 0;
        __syncthreads();
        sp[t] += u;
        __syncthreads();
    }
    int excl = sp[t] - v + g_bsum[blockIdx.x];
    if (i < NN) { g_off[i] = excl; g_woff[i] = excl; }
}

// scatter: sources grouped by target
__global__ void k_scatter(const int* __restrict__ ei) {
    int e = blockIdx.x * blockDim.x + threadIdx.x;
    if (e >= TOTE) return;
    int s, t;
    if (e < EE) { s = ei[e]; t = ei[EE + e]; }
    else        { s = t = e - EE; }
    if ((unsigned)t >= NN || (unsigned)s >= NN) return;
    int pos = atomicAdd(&g_woff[t], 1);
    if ((unsigned)pos < TOTE) g_srcs[pos] = s;
}

// fused: segment softmax + weighted gather + bias/relu/FC(256->3)/log_softmax
__global__ void k_node(const float* __restrict__ bias, const float* __restrict__ fcw,
                       const float* __restrict__ fcb) {
    int n    = (blockIdx.x * blockDim.x + threadIdx.x) >> 5;
    int lane = threadIdx.x & 31;
    if (n >= NN) return;
    int off = g_off[n], deg = g_deg[n];
    float ad0 = g_ad[2 * n], ad1 = g_ad[2 * n + 1];

    // pass A: leaky is monotone -> only need max over a_s[src]
    float mas0 = -INFINITY, mas1 = -INFINITY;
    for (int i = lane; i < deg; i += 32) {
        int s = g_srcs[off + i];
        mas0 = fmaxf(mas0, g_as[2 * s]);
        mas1 = fmaxf(mas1, g_as[2 * s + 1]);
    }
#pragma unroll
    for (int o = 16; o; o >>= 1) {
        mas0 = fmaxf(mas0, __shfl_xor_sync(0xffffffffu, mas0, o));
        mas1 = fmaxf(mas1, __shfl_xor_sync(0xffffffffu, mas1, o));
    }
    float m0 = mas0 + ad0; m0 = m0 > 0.f ? m0 : 0.2f * m0;
    float m1 = mas1 + ad1; m1 = m1 > 0.f ? m1 : 0.2f * m1;

    bool head0 = lane < 16;
    float acc[8] = {0, 0, 0, 0, 0, 0, 0, 0};
    float den0 = 0.f, den1 = 0.f;

    for (int i0 = 0; i0 < deg; i0 += 32) {
        int cnt = min(32, deg - i0);
        int s = 0; float ex0 = 0.f, ex1 = 0.f;
        if (lane < cnt) {
            s = g_srcs[off + i0 + lane];
            float l0 = g_as[2 * s]     + ad0; l0 = l0 > 0.f ? l0 : 0.2f * l0;
            float l1 = g_as[2 * s + 1] + ad1; l1 = l1 > 0.f ? l1 : 0.2f * l1;
            ex0 = expf(l0 - m0);
            ex1 = expf(l1 - m1);
        }
        den0 += ex0; den1 += ex1;
        for (int j = 0; j < cnt; j++) {
            int   sj = __shfl_sync(0xffffffffu, s,   j);
            float e0 = __shfl_sync(0xffffffffu, ex0, j);
            float e1 = __shfl_sync(0xffffffffu, ex1, j);
            float exj = head0 ? e0 : e1;
            const float4* xsrc = g_xw4 + sj * 64 + lane * 2;
            float4 v0 = xsrc[0], v1 = xsrc[1];
            acc[0] += exj * v0.x; acc[1] += exj * v0.y;
            acc[2] += exj * v0.z; acc[3] += exj * v0.w;
            acc[4] += exj * v1.x; acc[5] += exj * v1.y;
            acc[6] += exj * v1.z; acc[7] += exj * v1.w;
        }
    }
#pragma unroll
    for (int o = 16; o; o >>= 1) {
        den0 += __shfl_xor_sync(0xffffffffu, den0, o);
        den1 += __shfl_xor_sync(0xffffffffu, den1, o);
    }
    float inv = 1.f / (head0 ? den0 : den1);

    int colbase = lane * 8;
    float z0 = 0.f, z1 = 0.f, z2 = 0.f;
#pragma unroll
    for (int m = 0; m < 8; m++) {
        float val = acc[m] * inv + bias[colbase + m];
        val = val > 0.f ? val : 0.f;
        int k = colbase + m;
        z0 += val * fcw[k * 3 + 0];
        z1 += val * fcw[k * 3 + 1];
        z2 += val * fcw[k * 3 + 2];
    }
#pragma unroll
    for (int o = 16; o; o >>= 1) {
        z0 += __shfl_xor_sync(0xffffffffu, z0, o);
        z1 += __shfl_xor_sync(0xffffffffu, z1, o);
        z2 += __shfl_xor_sync(0xffffffffu, z2, o);
    }
    if (lane == 0) {
        z0 += fcb[0]; z1 += fcb[1]; z2 += fcb[2];
        float mx = fmaxf(z0, fmaxf(z1, z2));
        float ls = mx + logf(expf(z0 - mx) + expf(z1 - mx) + expf(z2 - mx));
        g_z[n * 3 + 0] = z0 - ls;
        g_z[n * 3 + 1] = z1 - ls;
        g_z[n * 3 + 2] = z2 - ls;
    }
}

// deterministic pool: batch sorted -> contiguous node range per graph.
__global__ void k_pool(const int* __restrict__ batch, const float* __restrict__ a,
                       float* __restrict__ out) {
    __shared__ float sz[3][256];
    int g = blockIdx.x;
    int t = threadIdx.x;
    int lo = 0, hi = NN;
    while (lo < hi) { int mid = (lo + hi) >> 1; if (batch[mid] < g) lo = mid + 1; else hi = mid; }
    int s0 = lo;
    hi = NN;
    while (lo < hi) { int mid = (lo + hi) >> 1; if (batch[mid] < g + 1) lo = mid + 1; else hi = mid; }
    int e0 = lo;

    float z0 = 0.f, z1 = 0.f, z2 = 0.f;
    for (int n = s0 + t; n < e0; n += 256) {
        z0 += g_z[n * 3 + 0];
        z1 += g_z[n * 3 + 1];
        z2 += g_z[n * 3 + 2];
    }
    sz[0][t] = z0; sz[1][t] = z1; sz[2][t] = z2;
    __syncthreads();
    for (int off = 128; off; off >>= 1) {
        if (t < off) {
            sz[0][t] += sz[0][t + off];
            sz[1][t] += sz[1][t + off];
            sz[2][t] += sz[2][t + off];
        }
        __syncthreads();
    }
    if (t == 0) {
        float sc = *a;
        float p0 = sc * sz[0][0], p1 = sc * sz[1][0], p2 = sc * sz[2][0];
        float mx = fmaxf(p0, fmaxf(p1, p2));
        float ls = mx + logf(expf(p0 - mx) + expf(p1 - mx) + expf(p2 - mx));
        out[g * 3 + 0] = p0 - ls;
        out[g * 3 + 1] = p1 - ls;
        out[g * 3 + 2] = p2 - ls;
    }
}

// ---------------- launch -----------------------------------------------------
extern "C" void kernel_launch(void* const* d_in, const int* in_sizes, int n_in,
                              void* d_out, int out_size) {
    const float* x     = (const float*)d_in[0];
    const int*   ei    = (const int*)d_in[1];
    const int*   batch = (const int*)d_in[2];
    const float* W     = (const float*)d_in[3];
    const float* att_s = (const float*)d_in[4];
    const float* att_d = (const float*)d_in[5];
    const float* bias  = (const float*)d_in[6];
    const float* fcw   = (const float*)d_in[7];
    const float* fcb   = (const float*)d_in[8];
    const float* a     = (const float*)d_in[9];
    float* out = (float*)d_out;

    const int SMEM = (128 * 68 + 32 * 256) * 4;   // 67584 B
    cudaFuncSetAttribute(k_gemm, cudaFuncAttributeMaxDynamicSharedMemorySize, SMEM);

    k_init   <<<(NN + 255) / 256, 256>>>();
    k_gemm   <<<(NN + 63) / 64, 256, SMEM>>>(x, W, att_s, att_d);
    k_deg    <<<(TOTE + 255) / 256, 256>>>(ei);
    k_scan1  <<<NB_SCAN, 256>>>();
    k_scan2  <<<1, 256>>>();
    k_scan3  <<<NB_SCAN, 256>>>();
    k_scatter<<<(TOTE + 255) / 256, 256>>>(ei);
    k_node   <<<(NN + 7) / 8, 256>>>(bias, fcw, fcb);
    k_pool   <<<GG, 256>>>(batch, a, out);
}

// round 8
// speedup vs baseline: 1.0032x; 1.0032x over previous
#include <cuda_runtime.h>
#include <math.h>

#define NN   50000
#define EE   300000
#define TOTE (EE + NN)
#define GG   64
#define NB_SCAN 196   // ceil(NN/256)

typedef unsigned long long u64;

// ---------------- scratch (device globals; no allocation allowed) ----------
__device__ float4 g_xw4[NN * 64];   // x @ W   [N, 256] viewed as [N, 64] float4
__device__ float  g_as[NN * 2];
__device__ float  g_ad[NN * 2];
__device__ int    g_deg[NN];
__device__ int    g_off[NN];
__device__ int    g_woff[NN];
__device__ int    g_srcs[TOTE];
__device__ float  g_z[NN * 3];
__device__ int    g_bsum[256];

// ---------------- packed f32x2 helpers ---------------------------------------
__device__ __forceinline__ void fma2(u64& d, u64 a, u64 b) {
    asm("fma.rn.f32x2 %0, %1, %2, %0;" : "+l"(d) : "l"(a), "l"(b));
}
__device__ __forceinline__ u64 bcast2(float x) {
    u64 r;
    asm("mov.b64 %0, {%1, %1};" : "=l"(r) : "f"(x));
    return r;
}
__device__ __forceinline__ void unpack2(u64 v, float& lo, float& hi) {
    asm("mov.b64 {%0, %1}, %2;" : "=f"(lo), "=f"(hi) : "l"(v));
}

// ---------------- kernels ----------------------------------------------------
__global__ void k_init() {
    int i = blockIdx.x * blockDim.x + threadIdx.x;
    if (i < NN) g_deg[i] = 0;
}

// degree histogram of targets
__global__ void k_deg(const int* __restrict__ ei) {
    int e = blockIdx.x * blockDim.x + threadIdx.x;
    if (e >= TOTE) return;
    int t = (e < EE) ? ei[EE + e] : (e - EE);
    if ((unsigned)t < NN) atomicAdd(&g_deg[t], 1);
}

// scan stage 1: per-block sums
__global__ void k_scan1() {
    __shared__ int sp[256];
    int t = threadIdx.x;
    int i = blockIdx.x * 256 + t;
    sp[t] = (i < NN) ? g_deg[i] : 0;
    __syncthreads();
    for (int off = 128; off; off >>= 1) {
        if (t < off) sp[t] += sp[t + off];
        __syncthreads();
    }
    if (t == 0) g_bsum[blockIdx.x] = sp[0];
}

// Tiled GEMM with packed f32x2 FMA: 64 nodes x 256 cols per block;
// thread = 8 nodes x 8 cols (4 packed col-pairs). Fused a_s/a_d epilogue.
// (4th submitted launch -> gets profiled by the harness's ncu -s 5 -c 1)
__global__ __launch_bounds__(256) void k_gemm(const float* __restrict__ x,
                                              const float* __restrict__ W,
                                              const float* __restrict__ att_s,
                                              const float* __restrict__ att_d) {
    extern __shared__ float sm[];
    float* xs = sm;                 // [128][68], xs[k*68 + node]
    float* ws = sm + 128 * 68;      // [32][256]

    int tid = threadIdx.x;
    int tx = tid & 31;              // col group: cols tx*8 .. tx*8+7
    int ty = tid >> 5;              // node group: nodes ty*8 .. +7
    int n0 = blockIdx.x * 64;

    // load x tile transposed (zero-pad past NN)
#pragma unroll
    for (int r = 0; r < 8; r++) {
        int lin4 = r * 256 + tid;
        int node = lin4 >> 5;
        int k = (lin4 & 31) * 4;
        float4 v = make_float4(0.f, 0.f, 0.f, 0.f);
        if (n0 + node < NN) v = ((const float4*)x)[(size_t)(n0 + node) * 32 + (lin4 & 31)];
        xs[(k + 0) * 68 + node] = v.x;
        xs[(k + 1) * 68 + node] = v.y;
        xs[(k + 2) * 68 + node] = v.z;
        xs[(k + 3) * 68 + node] = v.w;
    }

    u64 acc2[8][4];
#pragma unroll
    for (int i = 0; i < 8; i++)
#pragma unroll
        for (int j = 0; j < 4; j++) acc2[i][j] = 0ull;

    for (int kc = 0; kc < 4; kc++) {
        __syncthreads();
#pragma unroll
        for (int r = 0; r < 8; r++) {
            int lin4 = r * 256 + tid;
            ((float4*)ws)[lin4] = ((const float4*)W)[kc * 2048 + lin4];
        }
        __syncthreads();
#pragma unroll 8
        for (int k = 0; k < 32; k++) {
            const float* xr = &xs[(kc * 32 + k) * 68 + ty * 8];
            float4 a0 = *(const float4*)(xr);
            float4 a1 = *(const float4*)(xr + 4);
            u64 xp[8] = {bcast2(a0.x), bcast2(a0.y), bcast2(a0.z), bcast2(a0.w),
                         bcast2(a1.x), bcast2(a1.y), bcast2(a1.z), bcast2(a1.w)};
            const u64* wr = (const u64*)&ws[k * 256 + tx * 8];
            u64 w0 = wr[0], w1 = wr[1], w2 = wr[2], w3 = wr[3];
#pragma unroll
            for (int i = 0; i < 8; i++) {
                fma2(acc2[i][0], xp[i], w0);
                fma2(acc2[i][1], xp[i], w1);
                fma2(acc2[i][2], xp[i], w2);
                fma2(acc2[i][3], xp[i], w3);
            }
        }
    }

    // unpack accumulators, then epilogue: store xw + fused a_s/a_d
    int head = (tx < 16) ? 0 : 1;
    float4 s0 = ((const float4*)att_s)[tx * 2];
    float4 s1 = ((const float4*)att_s)[tx * 2 + 1];
    float4 d0 = ((const float4*)att_d)[tx * 2];
    float4 d1 = ((const float4*)att_d)[tx * 2 + 1];
#pragma unroll
    for (int i = 0; i < 8; i++) {
        float acc[8];
#pragma unroll
        for (int j = 0; j < 4; j++) unpack2(acc2[i][j], acc[2 * j], acc[2 * j + 1]);
        int node = n0 + ty * 8 + i;
        float sp = acc[0] * s0.x + acc[1] * s0.y + acc[2] * s0.z + acc[3] * s0.w
                 + acc[4] * s1.x + acc[5] * s1.y + acc[6] * s1.z + acc[7] * s1.w;
        float dp = acc[0] * d0.x + acc[1] * d0.y + acc[2] * d0.z + acc[3] * d0.w
                 + acc[4] * d1.x + acc[5] * d1.y + acc[6] * d1.z + acc[7] * d1.w;
#pragma unroll
        for (int off = 1; off < 16; off <<= 1) {
            sp += __shfl_xor_sync(0xffffffffu, sp, off);
            dp += __shfl_xor_sync(0xffffffffu, dp, off);
        }
        if (node < NN) {
            g_xw4[(size_t)node * 64 + tx * 2]     = make_float4(acc[0], acc[1], acc[2], acc[3]);
            g_xw4[(size_t)node * 64 + tx * 2 + 1] = make_float4(acc[4], acc[5], acc[6], acc[7]);
            if ((tx & 15) == 0) {
                g_as[2 * node + head] = sp;
                g_ad[2 * node + head] = dp;
            }
        }
    }
}

// scan stage 2+3 fused: every block redundantly scans the 196 block sums
// in smem, picks its own exclusive base, then does its local scan.
__global__ void k_scanB() {
    __shared__ int sb[256];
    __shared__ int sp[256];
    int t = threadIdx.x;
    int b = blockIdx.x;

    sb[t] = (t < NB_SCAN) ? g_bsum[t] : 0;
    __syncthreads();
    for (int off = 1; off < 256; off <<= 1) {
        int u = (t >= off) ? sb[t - off] : 0;
        __syncthreads();
        sb[t] += u;
        __syncthreads();
    }
    int base = (b == 0) ? 0 : sb[b - 1];   // exclusive prefix of block sums

    int i = b * 256 + t;
    int v = (i < NN) ? g_deg[i] : 0;
    sp[t] = v;
    __syncthreads();
    for (int off = 1; off < 256; off <<= 1) {
        int u = (t >= off) ? sp[t - off] : 0;
        __syncthreads();
        sp[t] += u;
        __syncthreads();
    }
    int excl = sp[t] - v + base;
    if (i < NN) { g_off[i] = excl; g_woff[i] = excl; }
}

// scatter: sources grouped by target
__global__ void k_scatter(const int* __restrict__ ei) {
    int e = blockIdx.x * blockDim.x + threadIdx.x;
    if (e >= TOTE) return;
    int s, t;
    if (e < EE) { s = ei[e]; t = ei[EE + e]; }
    else        { s = t = e - EE; }
    if ((unsigned)t >= NN || (unsigned)s >= NN) return;
    int pos = atomicAdd(&g_woff[t], 1);
    if ((unsigned)pos < TOTE) g_srcs[pos] = s;
}

// fused: segment softmax + weighted gather + bias/relu/FC(256->3)/log_softmax
__global__ void k_node(const float* __restrict__ bias, const float* __restrict__ fcw,
                       const float* __restrict__ fcb) {
    int n    = (blockIdx.x * blockDim.x + threadIdx.x) >> 5;
    int lane = threadIdx.x & 31;
    if (n >= NN) return;
    int off = g_off[n], deg = g_deg[n];
    float ad0 = g_ad[2 * n], ad1 = g_ad[2 * n + 1];

    // pass A: leaky is monotone -> only need max over a_s[src]
    float mas0 = -INFINITY, mas1 = -INFINITY;
    for (int i = lane; i < deg; i += 32) {
        int s = g_srcs[off + i];
        mas0 = fmaxf(mas0, g_as[2 * s]);
        mas1 = fmaxf(mas1, g_as[2 * s + 1]);
    }
#pragma unroll
    for (int o = 16; o; o >>= 1) {
        mas0 = fmaxf(mas0, __shfl_xor_sync(0xffffffffu, mas0, o));
        mas1 = fmaxf(mas1, __shfl_xor_sync(0xffffffffu, mas1, o));
    }
    float m0 = mas0 + ad0; m0 = m0 > 0.f ? m0 : 0.2f * m0;
    float m1 = mas1 + ad1; m1 = m1 > 0.f ? m1 : 0.2f * m1;

    bool head0 = lane < 16;
    float acc[8] = {0, 0, 0, 0, 0, 0, 0, 0};
    float den0 = 0.f, den1 = 0.f;

    for (int i0 = 0; i0 < deg; i0 += 32) {
        int cnt = min(32, deg - i0);
        int s = 0; float ex0 = 0.f, ex1 = 0.f;
        if (lane < cnt) {
            s = g_srcs[off + i0 + lane];
            float l0 = g_as[2 * s]     + ad0; l0 = l0 > 0.f ? l0 : 0.2f * l0;
            float l1 = g_as[2 * s + 1] + ad1; l1 = l1 > 0.f ? l1 : 0.2f * l1;
            ex0 = expf(l0 - m0);
            ex1 = expf(l1 - m1);
        }
        den0 += ex0; den1 += ex1;
        for (int j = 0; j < cnt; j++) {
            int   sj = __shfl_sync(0xffffffffu, s,   j);
            float e0 = __shfl_sync(0xffffffffu, ex0, j);
            float e1 = __shfl_sync(0xffffffffu, ex1, j);
            float exj = head0 ? e0 : e1;
            const float4* xsrc = g_xw4 + sj * 64 + lane * 2;
            float4 v0 = xsrc[0], v1 = xsrc[1];
            acc[0] += exj * v0.x; acc[1] += exj * v0.y;
            acc[2] += exj * v0.z; acc[3] += exj * v0.w;
            acc[4] += exj * v1.x; acc[5] += exj * v1.y;
            acc[6] += exj * v1.z; acc[7] += exj * v1.w;
        }
    }
#pragma unroll
    for (int o = 16; o; o >>= 1) {
        den0 += __shfl_xor_sync(0xffffffffu, den0, o);
        den1 += __shfl_xor_sync(0xffffffffu, den1, o);
    }
    float inv = 1.f / (head0 ? den0 : den1);

    int colbase = lane * 8;
    float z0 = 0.f, z1 = 0.f, z2 = 0.f;
#pragma unroll
    for (int m = 0; m < 8; m++) {
        float val = acc[m] * inv + bias[colbase + m];
        val = val > 0.f ? val : 0.f;
        int k = colbase + m;
        z0 += val * fcw[k * 3 + 0];
        z1 += val * fcw[k * 3 + 1];
        z2 += val * fcw[k * 3 + 2];
    }
#pragma unroll
    for (int o = 16; o; o >>= 1) {
        z0 += __shfl_xor_sync(0xffffffffu, z0, o);
        z1 += __shfl_xor_sync(0xffffffffu, z1, o);
        z2 += __shfl_xor_sync(0xffffffffu, z2, o);
    }
    if (lane == 0) {
        z0 += fcb[0]; z1 += fcb[1]; z2 += fcb[2];
        float mx = fmaxf(z0, fmaxf(z1, z2));
        float ls = mx + logf(expf(z0 - mx) + expf(z1 - mx) + expf(z2 - mx));
        g_z[n * 3 + 0] = z0 - ls;
        g_z[n * 3 + 1] = z1 - ls;
        g_z[n * 3 + 2] = z2 - ls;
    }
}

// deterministic pool: batch sorted -> contiguous node range per graph.
__global__ void k_pool(const int* __restrict__ batch, const float* __restrict__ a,
                       float* __restrict__ out) {
    __shared__ float sz[3][256];
    int g = blockIdx.x;
    int t = threadIdx.x;
    int lo = 0, hi = NN;
    while (lo < hi) { int mid = (lo + hi) >> 1; if (batch[mid] < g) lo = mid + 1; else hi = mid; }
    int s0 = lo;
    hi = NN;
    while (lo < hi) { int mid = (lo + hi) >> 1; if (batch[mid] < g + 1) lo = mid + 1; else hi = mid; }
    int e0 = lo;

    float z0 = 0.f, z1 = 0.f, z2 = 0.f;
    for (int n = s0 + t; n < e0; n += 256) {
        z0 += g_z[n * 3 + 0];
        z1 += g_z[n * 3 + 1];
        z2 += g_z[n * 3 + 2];
    }
    sz[0][t] = z0; sz[1][t] = z1; sz[2][t] = z2;
    __syncthreads();
    for (int off = 128; off; off >>= 1) {
        if (t < off) {
            sz[0][t] += sz[0][t + off];
            sz[1][t] += sz[1][t + off];
            sz[2][t] += sz[2][t + off];
        }
        __syncthreads();
    }
    if (t == 0) {
        float sc = *a;
        float p0 = sc * sz[0][0], p1 = sc * sz[1][0], p2 = sc * sz[2][0];
        float mx = fmaxf(p0, fmaxf(p1, p2));
        float ls = mx + logf(expf(p0 - mx) + expf(p1 - mx) + expf(p2 - mx));
        out[g * 3 + 0] = p0 - ls;
        out[g * 3 + 1] = p1 - ls;
        out[g * 3 + 2] = p2 - ls;
    }
}

// ---------------- launch -----------------------------------------------------
extern "C" void kernel_launch(void* const* d_in, const int* in_sizes, int n_in,
                              void* d_out, int out_size) {
    const float* x     = (const float*)d_in[0];
    const int*   ei    = (const int*)d_in[1];
    const int*   batch = (const int*)d_in[2];
    const float* W     = (const float*)d_in[3];
    const float* att_s = (const float*)d_in[4];
    const float* att_d = (const float*)d_in[5];
    const float* bias  = (const float*)d_in[6];
    const float* fcw   = (const float*)d_in[7];
    const float* fcb   = (const float*)d_in[8];
    const float* a     = (const float*)d_in[9];
    float* out = (float*)d_out;

    const int SMEM = (128 * 68 + 32 * 256) * 4;   // 67584 B
    cudaFuncSetAttribute(k_gemm, cudaFuncAttributeMaxDynamicSharedMemorySize, SMEM);

    // order chosen so k_gemm is the 4th launch (ncu capture slot)
    k_init   <<<(NN + 255) / 256, 256>>>();
    k_deg    <<<(TOTE + 255) / 256, 256>>>(ei);
    k_scan1  <<<NB_SCAN, 256>>>();
    k_gemm   <<<(NN + 63) / 64, 256, SMEM>>>(x, W, att_s, att_d);   // 4th: profiled
    k_scanB  <<<NB_SCAN, 256>>>();
    k_scatter<<<(TOTE + 255) / 256, 256>>>(ei);
    k_node   <<<(NN + 7) / 8, 256>>>(bias, fcw, fcb);
    k_pool   <<<GG, 256>>>(batch, a, out);
}

// round 9
// speedup vs baseline: 1.0308x; 1.0274x over previous
#include <cuda_runtime.h>
#include <math.h>

#define NN   50000
#define EE   300000
#define TOTE (EE + NN)
#define GG   64
#define NB_SCAN 196   // ceil(NN/256)

typedef unsigned long long u64;

// ---------------- scratch (device globals; no allocation allowed) ----------
__device__ float4 g_xw4[NN * 64];   // x @ W   [N, 256] viewed as [N, 64] float4
__device__ float  g_as[NN * 2];
__device__ float  g_ad[NN * 2];
__device__ int    g_deg[NN];
__device__ int    g_off[NN];
__device__ int    g_woff[NN];
__device__ int    g_srcs[TOTE];
__device__ float  g_z[NN * 3];
__device__ int    g_bsum[256];

// ---------------- packed f32x2 helpers ---------------------------------------
__device__ __forceinline__ void fma2(u64& d, u64 a, u64 b) {
    asm("fma.rn.f32x2 %0, %1, %2, %0;" : "+l"(d) : "l"(a), "l"(b));
}
__device__ __forceinline__ u64 bcast2(float x) {
    u64 r;
    asm("mov.b64 %0, {%1, %1};" : "=l"(r) : "f"(x));
    return r;
}
__device__ __forceinline__ u64 pk2(float lo, float hi) {
    u64 r;
    asm("mov.b64 %0, {%1, %2};" : "=l"(r) : "f"(lo), "f"(hi));
    return r;
}
__device__ __forceinline__ void unpack2(u64 v, float& lo, float& hi) {
    asm("mov.b64 {%0, %1}, %2;" : "=f"(lo), "=f"(hi) : "l"(v));
}

// ---------------- kernels ----------------------------------------------------
__global__ void k_init() {
    int i = blockIdx.x * blockDim.x + threadIdx.x;
    if (i < NN) g_deg[i] = 0;
}

// degree histogram of targets
__global__ void k_deg(const int* __restrict__ ei) {
    int e = blockIdx.x * blockDim.x + threadIdx.x;
    if (e >= TOTE) return;
    int t = (e < EE) ? ei[EE + e] : (e - EE);
    if ((unsigned)t < NN) atomicAdd(&g_deg[t], 1);
}

// scan stage 1: per-block sums
__global__ void k_scan1() {
    __shared__ int sp[256];
    int t = threadIdx.x;
    int i = blockIdx.x * 256 + t;
    sp[t] = (i < NN) ? g_deg[i] : 0;
    __syncthreads();
    for (int off = 128; off; off >>= 1) {
        if (t < off) sp[t] += sp[t + off];
        __syncthreads();
    }
    if (t == 0) g_bsum[blockIdx.x] = sp[0];
}

// Tiled GEMM, f32x2 FMA, conflict-free W reads.
// Block: 64 nodes x 256 cols. Thread: 8 nodes x 8 cols, where the 8 cols are
// {tx*4..tx*4+3} (head0) and {128+tx*4..128+tx*4+3} (head1): lane stride 16B
// -> LDS.128 with zero bank conflicts. Fused a_s/a_d epilogue.
__global__ __launch_bounds__(256) void k_gemm(const float* __restrict__ x,
                                              const float* __restrict__ W,
                                              const float* __restrict__ att_s,
                                              const float* __restrict__ att_d) {
    extern __shared__ float sm[];
    float* xs = sm;                 // [128][68], xs[k*68 + node]
    float* ws = sm + 128 * 68;      // [32][256]

    int tid = threadIdx.x;
    int tx = tid & 31;
    int ty = tid >> 5;              // node group: nodes ty*8 .. +7
    int n0 = blockIdx.x * 64;

    // load x tile transposed (zero-pad past NN)
#pragma unroll
    for (int r = 0; r < 8; r++) {
        int lin4 = r * 256 + tid;
        int node = lin4 >> 5;
        int k = (lin4 & 31) * 4;
        float4 v = make_float4(0.f, 0.f, 0.f, 0.f);
        if (n0 + node < NN) v = ((const float4*)x)[(size_t)(n0 + node) * 32 + (lin4 & 31)];
        xs[(k + 0) * 68 + node] = v.x;
        xs[(k + 1) * 68 + node] = v.y;
        xs[(k + 2) * 68 + node] = v.z;
        xs[(k + 3) * 68 + node] = v.w;
    }

    u64 acc2[8][4];
#pragma unroll
    for (int i = 0; i < 8; i++)
#pragma unroll
        for (int j = 0; j < 4; j++) acc2[i][j] = 0ull;

    for (int kc = 0; kc < 4; kc++) {
        __syncthreads();
#pragma unroll
        for (int r = 0; r < 8; r++) {
            int lin4 = r * 256 + tid;
            ((float4*)ws)[lin4] = ((const float4*)W)[kc * 2048 + lin4];
        }
        __syncthreads();
#pragma unroll 8
        for (int k = 0; k < 32; k++) {
            const float* xr = &xs[(kc * 32 + k) * 68 + ty * 8];
            float4 a0 = *(const float4*)(xr);
            float4 a1 = *(const float4*)(xr + 4);
            u64 xp[8] = {bcast2(a0.x), bcast2(a0.y), bcast2(a0.z), bcast2(a0.w),
                         bcast2(a1.x), bcast2(a1.y), bcast2(a1.z), bcast2(a1.w)};
            // conflict-free LDS.128 x2 (16B lane stride)
            float4 wa = *(const float4*)&ws[k * 256 + tx * 4];
            float4 wb = *(const float4*)&ws[k * 256 + 128 + tx * 4];
            u64 w0 = pk2(wa.x, wa.y), w1 = pk2(wa.z, wa.w);
            u64 w2 = pk2(wb.x, wb.y), w3 = pk2(wb.z, wb.w);
#pragma unroll
            for (int i = 0; i < 8; i++) {
                fma2(acc2[i][0], xp[i], w0);
                fma2(acc2[i][1], xp[i], w1);
                fma2(acc2[i][2], xp[i], w2);
                fma2(acc2[i][3], xp[i], w3);
            }
        }
    }

    // epilogue: store xw + fused a_s/a_d (head0 = cols tx*4.., head1 = 128+tx*4..)
    float4 s0 = *(const float4*)&att_s[tx * 4];
    float4 s1 = *(const float4*)&att_s[128 + tx * 4];
    float4 d0 = *(const float4*)&att_d[tx * 4];
    float4 d1 = *(const float4*)&att_d[128 + tx * 4];
#pragma unroll
    for (int i = 0; i < 8; i++) {
        float a[8];
#pragma unroll
        for (int j = 0; j < 4; j++) unpack2(acc2[i][j], a[2 * j], a[2 * j + 1]);
        int node = n0 + ty * 8 + i;
        float sp0 = a[0] * s0.x + a[1] * s0.y + a[2] * s0.z + a[3] * s0.w;
        float sp1 = a[4] * s1.x + a[5] * s1.y + a[6] * s1.z + a[7] * s1.w;
        float dp0 = a[0] * d0.x + a[1] * d0.y + a[2] * d0.z + a[3] * d0.w;
        float dp1 = a[4] * d1.x + a[5] * d1.y + a[6] * d1.z + a[7] * d1.w;
#pragma unroll
        for (int off = 16; off; off >>= 1) {
            sp0 += __shfl_xor_sync(0xffffffffu, sp0, off);
            sp1 += __shfl_xor_sync(0xffffffffu, sp1, off);
            dp0 += __shfl_xor_sync(0xffffffffu, dp0, off);
            dp1 += __shfl_xor_sync(0xffffffffu, dp1, off);
        }
        if (node < NN) {
            g_xw4[(size_t)node * 64 + tx]      = make_float4(a[0], a[1], a[2], a[3]);
            g_xw4[(size_t)node * 64 + 32 + tx] = make_float4(a[4], a[5], a[6], a[7]);
            if (tx == 0) {
                g_as[2 * node]     = sp0;
                g_as[2 * node + 1] = sp1;
                g_ad[2 * node]     = dp0;
                g_ad[2 * node + 1] = dp1;
            }
        }
    }
}

// scan stage 2+3 fused
__global__ void k_scanB() {
    __shared__ int sb[256];
    __shared__ int sp[256];
    int t = threadIdx.x;
    int b = blockIdx.x;

    sb[t] = (t < NB_SCAN) ? g_bsum[t] : 0;
    __syncthreads();
    for (int off = 1; off < 256; off <<= 1) {
        int u = (t >= off) ? sb[t - off] : 0;
        __syncthreads();
        sb[t] += u;
        __syncthreads();
    }
    int base = (b == 0) ? 0 : sb[b - 1];

    int i = b * 256 + t;
    int v = (i < NN) ? g_deg[i] : 0;
    sp[t] = v;
    __syncthreads();
    for (int off = 1; off < 256; off <<= 1) {
        int u = (t >= off) ? sp[t - off] : 0;
        __syncthreads();
        sp[t] += u;
        __syncthreads();
    }
    int excl = sp[t] - v + base;
    if (i < NN) { g_off[i] = excl; g_woff[i] = excl; }
}

// scatter: sources grouped by target
__global__ void k_scatter(const int* __restrict__ ei) {
    int e = blockIdx.x * blockDim.x + threadIdx.x;
    if (e >= TOTE) return;
    int s, t;
    if (e < EE) { s = ei[e]; t = ei[EE + e]; }
    else        { s = t = e - EE; }
    if ((unsigned)t >= NN || (unsigned)s >= NN) return;
    int pos = atomicAdd(&g_woff[t], 1);
    if ((unsigned)pos < TOTE) g_srcs[pos] = s;
}

// fused: segment softmax + weighted gather + bias/relu/FC(256->3)/log_softmax
// one warp per node; 2-stage prefetch in the edge loop to cover L2 latency.
__global__ void k_node(const float* __restrict__ bias, const float* __restrict__ fcw,
                       const float* __restrict__ fcb) {
    int n    = (blockIdx.x * blockDim.x + threadIdx.x) >> 5;
    int lane = threadIdx.x & 31;
    if (n >= NN) return;
    int off = g_off[n], deg = g_deg[n];
    float ad0 = g_ad[2 * n], ad1 = g_ad[2 * n + 1];

    // pass A: leaky is monotone -> only need max over a_s[src]
    float mas0 = -INFINITY, mas1 = -INFINITY;
    for (int i = lane; i < deg; i += 32) {
        int s = g_srcs[off + i];
        mas0 = fmaxf(mas0, g_as[2 * s]);
        mas1 = fmaxf(mas1, g_as[2 * s + 1]);
    }
#pragma unroll
    for (int o = 16; o; o >>= 1) {
        mas0 = fmaxf(mas0, __shfl_xor_sync(0xffffffffu, mas0, o));
        mas1 = fmaxf(mas1, __shfl_xor_sync(0xffffffffu, mas1, o));
    }
    float m0 = mas0 + ad0; m0 = m0 > 0.f ? m0 : 0.2f * m0;
    float m1 = mas1 + ad1; m1 = m1 > 0.f ? m1 : 0.2f * m1;

    bool head0 = lane < 16;
    float acc[8] = {0, 0, 0, 0, 0, 0, 0, 0};
    float den0 = 0.f, den1 = 0.f;

    for (int i0 = 0; i0 < deg; i0 += 32) {
        int cnt = min(32, deg - i0);
        int s = 0; float ex0 = 0.f, ex1 = 0.f;
        if (lane < cnt) {
            s = g_srcs[off + i0 + lane];
            float l0 = g_as[2 * s]     + ad0; l0 = l0 > 0.f ? l0 : 0.2f * l0;
            float l1 = g_as[2 * s + 1] + ad1; l1 = l1 > 0.f ? l1 : 0.2f * l1;
            ex0 = expf(l0 - m0);
            ex1 = expf(l1 - m1);
        }
        den0 += ex0; den1 += ex1;

        // 2-stage pipelined gather: load edge j+1 while accumulating edge j
        int s0i = __shfl_sync(0xffffffffu, s, 0);
        const float4* xp = g_xw4 + (size_t)s0i * 64 + lane * 2;
        float4 v0 = xp[0], v1 = xp[1];
        for (int j = 0; j < cnt; j++) {
            float4 n0v, n1v;
            if (j + 1 < cnt) {
                int sn = __shfl_sync(0xffffffffu, s, j + 1);
                const float4* np = g_xw4 + (size_t)sn * 64 + lane * 2;
                n0v = np[0]; n1v = np[1];
            }
            float e0 = __shfl_sync(0xffffffffu, ex0, j);
            float e1 = __shfl_sync(0xffffffffu, ex1, j);
            float exj = head0 ? e0 : e1;
            acc[0] += exj * v0.x; acc[1] += exj * v0.y;
            acc[2] += exj * v0.z; acc[3] += exj * v0.w;
            acc[4] += exj * v1.x; acc[5] += exj * v1.y;
            acc[6] += exj * v1.z; acc[7] += exj * v1.w;
            if (j + 1 < cnt) { v0 = n0v; v1 = n1v; }
        }
    }
#pragma unroll
    for (int o = 16; o; o >>= 1) {
        den0 += __shfl_xor_sync(0xffffffffu, den0, o);
        den1 += __shfl_xor_sync(0xffffffffu, den1, o);
    }
    float inv = 1.f / (head0 ? den0 : den1);

    int colbase = lane * 8;
    float z0 = 0.f, z1 = 0.f, z2 = 0.f;
#pragma unroll
    for (int m = 0; m < 8; m++) {
        float val = acc[m] * inv + bias[colbase + m];
        val = val > 0.f ? val : 0.f;
        int k = colbase + m;
        z0 += val * fcw[k * 3 + 0];
        z1 += val * fcw[k * 3 + 1];
        z2 += val * fcw[k * 3 + 2];
    }
#pragma unroll
    for (int o = 16; o; o >>= 1) {
        z0 += __shfl_xor_sync(0xffffffffu, z0, o);
        z1 += __shfl_xor_sync(0xffffffffu, z1, o);
        z2 += __shfl_xor_sync(0xffffffffu, z2, o);
    }
    if (lane == 0) {
        z0 += fcb[0]; z1 += fcb[1]; z2 += fcb[2];
        float mx = fmaxf(z0, fmaxf(z1, z2));
        float ls = mx + logf(expf(z0 - mx) + expf(z1 - mx) + expf(z2 - mx));
        g_z[n * 3 + 0] = z0 - ls;
        g_z[n * 3 + 1] = z1 - ls;
        g_z[n * 3 + 2] = z2 - ls;
    }
}

// deterministic pool: batch sorted -> contiguous node range per graph.
__global__ void k_pool(const int* __restrict__ batch, const float* __restrict__ a,
                       float* __restrict__ out) {
    __shared__ float sz[3][256];
    int g = blockIdx.x;
    int t = threadIdx.x;
    int lo = 0, hi = NN;
    while (lo < hi) { int mid = (lo + hi) >> 1; if (batch[mid] < g) lo = mid + 1; else hi = mid; }
    int s0 = lo;
    hi = NN;
    while (lo < hi) { int mid = (lo + hi) >> 1; if (batch[mid] < g + 1) lo = mid + 1; else hi = mid; }
    int e0 = lo;

    float z0 = 0.f, z1 = 0.f, z2 = 0.f;
    for (int n = s0 + t; n < e0; n += 256) {
        z0 += g_z[n * 3 + 0];
        z1 += g_z[n * 3 + 1];
        z2 += g_z[n * 3 + 2];
    }
    sz[0][t] = z0; sz[1][t] = z1; sz[2][t] = z2;
    __syncthreads();
    for (int off = 128; off; off >>= 1) {
        if (t < off) {
            sz[0][t] += sz[0][t + off];
            sz[1][t] += sz[1][t + off];
            sz[2][t] += sz[2][t + off];
        }
        __syncthreads();
    }
    if (t == 0) {
        float sc = *a;
        float p0 = sc * sz[0][0], p1 = sc * sz[1][0], p2 = sc * sz[2][0];
        float mx = fmaxf(p0, fmaxf(p1, p2));
        float ls = mx + logf(expf(p0 - mx) + expf(p1 - mx) + expf(p2 - mx));
        out[g * 3 + 0] = p0 - ls;
        out[g * 3 + 1] = p1 - ls;
        out[g * 3 + 2] = p2 - ls;
    }
}

// ---------------- launch -----------------------------------------------------
extern "C" void kernel_launch(void* const* d_in, const int* in_sizes, int n_in,
                              void* d_out, int out_size) {
    const float* x     = (const float*)d_in[0];
    const int*   ei    = (const int*)d_in[1];
    const int*   batch = (const int*)d_in[2];
    const float* W     = (const float*)d_in[3];
    const float* att_s = (const float*)d_in[4];
    const float* att_d = (const float*)d_in[5];
    const float* bias  = (const float*)d_in[6];
    const float* fcw   = (const float*)d_in[7];
    const float* fcb   = (const float*)d_in[8];
    const float* a     = (const float*)d_in[9];
    float* out = (float*)d_out;

    const int SMEM = (128 * 68 + 32 * 256) * 4;   // 67584 B
    cudaFuncSetAttribute(k_gemm, cudaFuncAttributeMaxDynamicSharedMemorySize, SMEM);

    // order chosen so k_gemm is the 4th launch (ncu capture slot)
    k_init   <<<(NN + 255) / 256, 256>>>();
    k_deg    <<<(TOTE + 255) / 256, 256>>>(ei);
    k_scan1  <<<NB_SCAN, 256>>>();
    k_gemm   <<<(NN + 63) / 64, 256, SMEM>>>(x, W, att_s, att_d);   // 4th: profiled
    k_scanB  <<<NB_SCAN, 256>>>();
    k_scatter<<<(TOTE + 255) / 256, 256>>>(ei);
    k_node   <<<(NN + 7) / 8, 256>>>(bias, fcw, fcb);
    k_pool   <<<GG, 256>>>(batch, a, out);
}